// round 7
// baseline (speedup 1.0000x reference)
#include <cuda_runtime.h>
#include <math.h>
#include <stdint.h>

// Problem constants: B=64, C=8, H=256, M=32  -> B*C=512 images, 1024 modes/image
#define NIMG   512
#define NMODE  1024
#define NBIG   (NIMG * NMODE)          // 524288

// Output layout (tuple order, concatenated float32):
#define OFF_E    ((size_t)0)                   // modal_energies        [512,1024]
#define OFF_U    ((size_t)NBIG)                // modal_uncertainties   [512,1024]
#define OFF_F    ((size_t)(2*NBIG))            // energy_fractions      [512,1024]
#define OFF_W    ((size_t)(3*NBIG))            // weighted_importance   [512,1024]
#define OFF_US   ((size_t)(4*NBIG))            // uncertainty_spectrum  [1024]
#define OFF_ES   ((size_t)(4*NBIG + 1024))     // energy_spectrum       [1024]
#define OFF_ERR  ((size_t)(4*NBIG + 2048))     // modal_errors          [512,1024]
#define OFF_CAL  ((size_t)(5*NBIG + 2048))     // calibration_scores    [1024]

#define EPS 1e-8f

// Scratch: 32x32 complex modes for pred (tensor 0) and gt (tensor 1)
__device__ float g_modesR[2 * NIMG * NMODE];
__device__ float g_modesI[2 * NIMG * NMODE];

// ---------------------------------------------------------------------------
// Kernel 1: pruned 2-D DFT. One block per (tensor, image). Static smem only.
//
// Stage 1 (per 32-row chunk), quarter-folded over y<->256-y AND y<->128-y:
//   s_y = f[y]+f[256-y], d_y = f[y]-f[256-y]  (y=1..127)
//   For k2 even:  Gr = f0 + f128 + (-1)^{k/2} s64 + sum_{y=1..63}(s_y+s_{128-y})cos
//                 Gi = -sum_{y=1..63}(d_y-d_{128-y})sin
//   For k2 odd:   Gr = f0 - f128 + sum_{y=1..63}(s_y-s_{128-y})cos
//                 Gi = -(-1)^{(k-1)/2} d64 - sum_{y=1..63}(d_y+d_{128-y})sin
// Stage 2 (partial): F[k1,k2] += sum_{x in chunk} G[x,k2] e^{-2pi i k1 x/256}.
// Twiddles by per-thread phase recurrence seeded with sincospif (exact args).
// ---------------------------------------------------------------------------
#define G_STRIDE  36                       // padded (32 cols + 4) for LDS.128

__global__ __launch_bounds__(256) void fft_kernel(const float* __restrict__ pred,
                                                  const float* __restrict__ gt) {
    __shared__ float  f4[32 * 64 * 4];     // [row][y=0..63][se,de,so,do] = 32768 B (y=0 unused)
    __shared__ float4 spv[32];             // per row: {f0, f128, s64, d64}  (512 B)
    __shared__ float  Gcr[32 * G_STRIDE];  // chunk's G rows, real  (4608 B)
    __shared__ float  Gci[32 * G_STRIDE];  //                imag  (4608 B)

    const int blk = blockIdx.x;                          // tensor*512 + img
    const float* src = ((blk >> 9) ? gt : pred) + (size_t)(blk & 511) * 65536u;

    const int t    = threadIdx.x;
    const int w    = t >> 5;
    const int lane = t & 31;                             // lane == k2 (stage 1)
    const int rbase = w * 4;                             // 4 rows per warp per chunk

    // stage-1 twiddle seed: cis(2*pi*lane/256)
    float ck, sk;
    sincospif((float)lane * (1.0f / 128.0f), &sk, &ck);
    const int   par = lane & 1;                          // k2 parity
    const float sg  = (lane & 2) ? -1.0f : 1.0f;         // sign for s64/d64 term

    // stage-2 per-thread assignment: k1 = t>>3, k2 group = (t&7)*4
    const int k1 = t >> 3;
    const int k2 = (t & 7) << 2;
    float c1, s1;
    sincospif((float)k1 * (1.0f / 128.0f), &s1, &c1);    // cis(2*pi*k1/256)
    float c2 = 1.0f, s2 = 0.0f;                          // phase at x = 0
    float Fr[4] = {0.f, 0.f, 0.f, 0.f};
    float Fi[4] = {0.f, 0.f, 0.f, 0.f};

    for (int chunk = 0; chunk < 8; ++chunk) {
        const int x0 = chunk * 32;

        // ---- load + quarter-fold 32 rows ----
        for (int i = t; i < 2048; i += 256) {
            const int r = i >> 6;
            const int y = i & 63;
            const float* row = src + (size_t)(x0 + r) * 256;
            if (y == 0) {
                const float a0 = row[0], a64 = row[64];
                const float a128 = row[128], a192 = row[192];
                spv[r] = make_float4(a0, a128, a64 + a192, a64 - a192);
            } else {
                const float a  = row[y];
                const float b  = row[128 - y];
                const float cc = row[128 + y];
                const float dd = row[256 - y];
                const float s1_ = a + dd, s2_ = b + cc;
                const float d1_ = a - dd, d2_ = b - cc;
                *reinterpret_cast<float4*>(f4 + ((size_t)r * 64 + y) * 4) =
                    make_float4(s1_ + s2_, d1_ - d2_, s1_ - s2_, d1_ + d2_);
            }
        }
        __syncthreads();

        // ---- stage 1: warp w handles rows rbase..rbase+3, lane = k2 ----
        {
            float ar[4], ai[4];
            #pragma unroll
            for (int j = 0; j < 4; ++j) {
                const float4 sp = spv[rbase + j];
                if (par == 0) {
                    ar[j] = sp.x + sp.y + sg * sp.z;
                    ai[j] = 0.0f;
                } else {
                    ar[j] = sp.x - sp.y;
                    ai[j] = -sg * sp.w;
                }
            }
            float c = ck, s = sk;                        // phase at y = 1
            for (int y = 1; y < 64; ++y) {
                #pragma unroll
                for (int j = 0; j < 4; ++j) {
                    const float2 v = *reinterpret_cast<const float2*>(
                        f4 + ((size_t)(rbase + j) * 64 + y) * 4 + 2 * par);
                    ar[j] = fmaf(v.x,  c, ar[j]);
                    ai[j] = fmaf(-v.y, s, ai[j]);
                }
                const float cn = c * ck - s * sk;
                s = s * ck + c * sk;
                c = cn;
            }
            #pragma unroll
            for (int j = 0; j < 4; ++j) {
                Gcr[(rbase + j) * G_STRIDE + lane] = ar[j];
                Gci[(rbase + j) * G_STRIDE + lane] = ai[j];
            }
        }
        __syncthreads();

        // ---- stage 2 (partial over this chunk's 32 x values) ----
        #pragma unroll 4
        for (int xi = 0; xi < 32; ++xi) {
            float4 gr = *reinterpret_cast<const float4*>(Gcr + xi * G_STRIDE + k2);
            float4 gi = *reinterpret_cast<const float4*>(Gci + xi * G_STRIDE + k2);
            Fr[0] = fmaf(gr.x, c2, fmaf(gi.x,  s2, Fr[0]));
            Fi[0] = fmaf(gi.x, c2, fmaf(-gr.x, s2, Fi[0]));
            Fr[1] = fmaf(gr.y, c2, fmaf(gi.y,  s2, Fr[1]));
            Fi[1] = fmaf(gi.y, c2, fmaf(-gr.y, s2, Fi[1]));
            Fr[2] = fmaf(gr.z, c2, fmaf(gi.z,  s2, Fr[2]));
            Fi[2] = fmaf(gi.z, c2, fmaf(-gr.z, s2, Fi[2]));
            Fr[3] = fmaf(gr.w, c2, fmaf(gi.w,  s2, Fr[3]));
            Fi[3] = fmaf(gi.w, c2, fmaf(-gr.w, s2, Fi[3]));
            const float cn = c2 * c1 - s2 * s1;
            s2 = s2 * c1 + c2 * s1;
            c2 = cn;
        }
        __syncthreads();
    }

    const size_t base = (size_t)blk * NMODE + (size_t)k1 * 32 + k2;
    #pragma unroll
    for (int j = 0; j < 4; ++j) {
        g_modesR[base + j] = Fr[j];
        g_modesI[base + j] = Fi[j];
    }
}

// ---------------------------------------------------------------------------
// Kernel 2: per-mode MLP + energies + errors + per-image normalization.
// One block per image (512 blocks, 256 threads, 4 modes/thread).
// ---------------------------------------------------------------------------
__global__ __launch_bounds__(256) void mlp_kernel(
    const float* __restrict__ W1, const float* __restrict__ b1,
    const float* __restrict__ W2, const float* __restrict__ b2,
    const float* __restrict__ W3, const float* __restrict__ b3,
    float* __restrict__ out) {

    __shared__ float4 w1p[64];       // {W1[0][j], W1[1][j], b1[j], 0}
    __shared__ float  W2s[64 * 32];
    __shared__ float  b2s[32];
    __shared__ float  W3s[32];
    __shared__ float  b3s;
    __shared__ float  red[256];

    const int t   = threadIdx.x;
    const int img = blockIdx.x;

    if (t < 64) w1p[t] = make_float4(W1[t], W1[64 + t], b1[t], 0.0f);
    for (int i = t; i < 2048; i += 256) W2s[i] = W2[i];
    if (t < 32) { b2s[t] = b2[t]; W3s[t] = W3[t]; }
    if (t == 0) b3s = b3[0];
    __syncthreads();

    const float* PR = g_modesR + (size_t)img * NMODE;
    const float* PI = g_modesI + (size_t)img * NMODE;
    const float* GR = g_modesR + (size_t)(NIMG + img) * NMODE;
    const float* GI = g_modesI + (size_t)(NIMG + img) * NMODE;

    float en[4], un[4];
    float esum = 0.0f;

    #pragma unroll
    for (int q = 0; q < 4; ++q) {
        const int m = t + q * 256;
        const float fr = PR[m];
        const float fi = PI[m];
        const float e  = fr * fr + fi * fi;
        en[q] = e;
        esum += e;

        // MLP: 2 -> 64 (relu) -> 32 (relu) -> 1 (softplus)
        float acc[32];
        #pragma unroll
        for (int n = 0; n < 32; ++n) acc[n] = b2s[n];
        for (int j = 0; j < 64; ++j) {
            float4 wp = w1p[j];
            float h = fmaf(fr, wp.x, fmaf(fi, wp.y, wp.z));
            h = fmaxf(h, 0.0f);
            #pragma unroll
            for (int n4 = 0; n4 < 8; ++n4) {
                float4 wv = *reinterpret_cast<const float4*>(W2s + j * 32 + n4 * 4);
                acc[n4 * 4 + 0] = fmaf(h, wv.x, acc[n4 * 4 + 0]);
                acc[n4 * 4 + 1] = fmaf(h, wv.y, acc[n4 * 4 + 1]);
                acc[n4 * 4 + 2] = fmaf(h, wv.z, acc[n4 * 4 + 2]);
                acc[n4 * 4 + 3] = fmaf(h, wv.w, acc[n4 * 4 + 3]);
            }
        }
        float o = b3s;
        #pragma unroll
        for (int n = 0; n < 32; ++n) o = fmaf(fmaxf(acc[n], 0.0f), W3s[n], o);
        // softplus(o) = max(o,0) + log1p(exp(-|o|))
        const float u = fmaxf(o, 0.0f) + log1pf(expf(-fabsf(o)));
        un[q] = u;

        const float dr = fr - GR[m];
        const float di = fi - GI[m];
        const float err = dr * dr + di * di;

        const size_t base = (size_t)img * NMODE + m;
        out[OFF_E   + base] = e;
        out[OFF_U   + base] = u;
        out[OFF_ERR + base] = err;
    }

    // block reduce total modal energy
    red[t] = esum;
    __syncthreads();
    for (int st = 128; st > 0; st >>= 1) {
        if (t < st) red[t] += red[t + st];
        __syncthreads();
    }
    const float total = red[0] + EPS;

    #pragma unroll
    for (int q = 0; q < 4; ++q) {
        const int m = t + q * 256;
        const size_t base = (size_t)img * NMODE + m;
        const float frac = en[q] / total;
        out[OFF_F + base] = frac;
        out[OFF_W + base] = frac * un[q];
    }
}

// ---------------------------------------------------------------------------
// Kernel 3: per-mode reductions over the 512-image axis.
// Spectra (means) + Pearson calibration scores (fp64 one-pass sums).
// One block per mode (1024 blocks, 128 threads).
// ---------------------------------------------------------------------------
__global__ __launch_bounds__(128) void spec_kernel(float* __restrict__ out) {
    const int m = blockIdx.x;
    const int t = threadIdx.x;

    const float* U = out + OFF_U;
    const float* E = out + OFF_E;
    const float* R = out + OFF_ERR;

    double su = 0.0, se = 0.0, sr = 0.0, su2 = 0.0, sr2 = 0.0, sur = 0.0;
    for (int bc = t; bc < NIMG; bc += 128) {
        const size_t idx = (size_t)bc * NMODE + m;
        const double u = (double)U[idx];
        const double e = (double)E[idx];
        const double r = (double)R[idx];
        su += u; se += e; sr += r;
        su2 += u * u; sr2 += r * r; sur += u * r;
    }
    // warp reduce
    #pragma unroll
    for (int o = 16; o > 0; o >>= 1) {
        su  += __shfl_down_sync(0xffffffffu, su,  o);
        se  += __shfl_down_sync(0xffffffffu, se,  o);
        sr  += __shfl_down_sync(0xffffffffu, sr,  o);
        su2 += __shfl_down_sync(0xffffffffu, su2, o);
        sr2 += __shfl_down_sync(0xffffffffu, sr2, o);
        sur += __shfl_down_sync(0xffffffffu, sur, o);
    }
    __shared__ double sm[4][6];
    const int w = t >> 5, lane = t & 31;
    if (lane == 0) {
        sm[w][0] = su;  sm[w][1] = se;  sm[w][2] = sr;
        sm[w][3] = su2; sm[w][4] = sr2; sm[w][5] = sur;
    }
    __syncthreads();
    if (t == 0) {
        double a[6];
        #pragma unroll
        for (int i = 0; i < 6; ++i)
            a[i] = sm[0][i] + sm[1][i] + sm[2][i] + sm[3][i];
        const double n = (double)NIMG;
        out[OFF_US + m] = (float)(a[0] / n);
        out[OFF_ES + m] = (float)(a[1] / n);
        const double num = a[5] - a[0] * a[2] / n;
        const double vu  = a[3] - a[0] * a[0] / n;
        const double vr  = a[4] - a[2] * a[2] / n;
        const double den = sqrt(vu * vr);
        out[OFF_CAL + m] = (float)(num / (den + (double)EPS));
    }
}

// ---------------------------------------------------------------------------
// Launch — pure kernel launches, no attribute calls, no dynamic smem.
// Inputs (metadata order): prediction, uncertainty(unused), ground_truth,
//                          W1, b1, W2, b2, W3, b3
// ---------------------------------------------------------------------------
extern "C" void kernel_launch(void* const* d_in, const int* in_sizes, int n_in,
                              void* d_out, int out_size) {
    const float* pred = (const float*)d_in[0];
    const float* gt   = (const float*)d_in[2];
    const float* W1   = (const float*)d_in[3];
    const float* b1   = (const float*)d_in[4];
    const float* W2   = (const float*)d_in[5];
    const float* b2   = (const float*)d_in[6];
    const float* W3   = (const float*)d_in[7];
    const float* b3   = (const float*)d_in[8];
    float* out = (float*)d_out;

    fft_kernel<<<2 * NIMG, 256>>>(pred, gt);
    mlp_kernel<<<NIMG, 256>>>(W1, b1, W2, b2, W3, b3, out);
    spec_kernel<<<NMODE, 128>>>(out);
}